// round 15
// baseline (speedup 1.0000x reference)
#include <cuda_runtime.h>
#include <cuda_fp16.h>
#include <cstdint>

// Problem dims
#define B_   1024
#define T_   256
#define D_   64
#define U_   512
#define HS   (B_*U_)
#define NG   2048          // 4*U_ gate columns (n' = 4u+g interleaved)
#define K1   (D_ + U_)     // 576
#define K2   (2*U_)        // 1024

#define NT   544                      // 16 consumer warps + 1 DMA warp
#define NCW  16                       // consumer warps
#define NBLK 128
#define NCH1 9                        // 1 x-chunk + 8 h1-chunks (64 k each)
#define NCH2 16                       // 8 h1-chunks + 8 h2-chunks
#define NSLOT 6                       // pipeline slots (1 chunk each)
#define TILE16 16384                  // one 128x64 fp16 tile (128B rows, SW128)
#define STAGE_B 32768                 // A tile + B tile
#define SM_TILES 1024                 // mbars in [0, 96): full[i]@16i, empty[i]@16i+8
#define SMEM_DYN (SM_TILES + NSLOT*STAGE_B)   // 197632 B (1 CTA/SM)

// A-chunk (h/x): [chunk][1024 m][64] = 65536 elems, swizzled 128B rows
#define ACH_E 65536
// B-chunk (weights): [chunk][2048 n'][64] = 131072 elems
#define BCH_E 131072

// ---------------- device globals (no allocations allowed) ----------------
__device__ __align__(16) __half g_B1[NG*K1], g_B2[NG*K2];
__device__ __align__(16) __half g_xf[T_*B_*D_];            // [t][m][64] sw
__device__ __align__(16) __half g_h1[2*HS], g_h2[2*HS];    // [buf][8ch][m][64] sw
__device__ __align__(16) float g_c1[HS], g_c2[HS], g_h2f[HS];

// Software grid barrier (monotonic generation; reset each replay)
__device__ unsigned g_count;
__device__ volatile unsigned g_gen;

__device__ __forceinline__ void grid_sync(unsigned gen)
{
    __syncthreads();
    if (threadIdx.x == 0) {
        __threadfence();
        unsigned prev = atomicAdd(&g_count, 1u);
        if (prev == gen * NBLK - 1u) {
            __threadfence();
            g_gen = gen;
        } else {
            while (g_gen < gen) { }
            __threadfence();
        }
    }
    __syncthreads();
}

__device__ __host__ __forceinline__ uint32_t SWZb(uint32_t o) { return o ^ ((o >> 3) & 0x70); }

__device__ __forceinline__ float sigmoidf_(float x) { return 1.0f / (1.0f + __expf(-x)); }
__device__ __forceinline__ float tanhf_(float x) {
    float y; asm("tanh.approx.f32 %0, %1;" : "=f"(y) : "f"(x)); return y;
}
__device__ __forceinline__ uint32_t smem_u32(const void* p) {
    return (uint32_t)__cvta_generic_to_shared(p);
}

#define LDSM4(r0, r1, r2, r3, addr) \
    asm volatile("ldmatrix.sync.aligned.m8n8.x4.shared.b16 {%0,%1,%2,%3}, [%4];" \
        : "=r"(r0), "=r"(r1), "=r"(r2), "=r"(r3) : "r"(addr))

#define MMA16816(c, a, b0_, b1_) \
    asm volatile("mma.sync.aligned.m16n8k16.row.col.f32.f16.f16.f32 " \
        "{%0,%1,%2,%3}, {%4,%5,%6,%7}, {%8,%9}, {%0,%1,%2,%3};" \
        : "+f"((c)[0]), "+f"((c)[1]), "+f"((c)[2]), "+f"((c)[3]) \
        : "r"((a)[0]), "r"((a)[1]), "r"((a)[2]), "r"((a)[3]), "r"(b0_), "r"(b1_))

#define MBAR_INIT(m, cnt) \
    asm volatile("mbarrier.init.shared.b64 [%0], %1;" :: "r"(m), "r"(cnt) : "memory")
#define MBAR_EXPECT_TX(m, bytes) \
    asm volatile("mbarrier.arrive.expect_tx.shared.b64 _, [%0], %1;" :: "r"(m), "r"(bytes) : "memory")
#define MBAR_ARRIVE(m) \
    asm volatile("mbarrier.arrive.shared.b64 _, [%0];" :: "r"(m) : "memory")
#define BULK_LD(dst, src, bytes, m) \
    asm volatile("cp.async.bulk.shared::cta.global.mbarrier::complete_tx::bytes [%0], [%1], %2, [%3];" \
        :: "r"(dst), "l"(src), "r"(bytes), "r"(m) : "memory")

__device__ __forceinline__ void mbar_wait(uint32_t m, uint32_t parity)
{
    asm volatile(
        "{\n\t.reg .pred P;\n\t"
        "WL_%=:\n\t"
        "mbarrier.try_wait.parity.acquire.cta.shared::cta.b64 P, [%0], %1, 0x989680;\n\t"
        "@!P bra WL_%=;\n\t}"
        :: "r"(m), "r"(parity) : "memory");
}

struct JobP { int nch; int a0n; const __half *a0, *a1, *Bw; };

// ---------------- persistent kernel: fused phases + dense head --------------
__global__ __launch_bounds__(NT, 1)
void lstm_persistent(const float* __restrict__ b1, const float* __restrict__ b2,
                     const float* __restrict__ Wd, const float* __restrict__ bd,
                     float* __restrict__ out)
{
    extern __shared__ __align__(1024) char smem[];
    const uint32_t sbase = smem_u32(smem);

    const int tid  = threadIdx.x;
    const int lane = tid & 31;
    const int ww   = tid >> 5;        // 0..16 (16 = DMA warp)
    const int wm   = ww & 3;          // m group (32 rows), consumer warps only
    const int wn   = (ww >> 2) & 3;   // n group (32 n' cols)
    const int n0 = (blockIdx.x & 15) * 128;
    const int m0 = (blockIdx.x >> 4) * 128;
    const int u0 = (blockIdx.x & 15) * 32;

    // persistent mbarriers: full[i] (1 tx-arrive), empty[i] (16 consumer-warp arrives)
    if (tid == 0)
        for (int i = 0; i < NSLOT; i++) {
            MBAR_INIT(sbase + i * 16, 1);
            MBAR_INIT(sbase + i * 16 + 8, NCW);
        }
    __syncthreads();

    int pslot = 0, pph = 1;   // producer cursor (waits empty; fresh barrier passes @parity 1)
    int cslot = 0, cph = 0;   // consumer cursor (waits full)

    float acc[2][4][4];
    auto zero_acc = [&] {
        #pragma unroll
        for (int i = 0; i < 2; i++)
            #pragma unroll
            for (int j = 0; j < 4; j++)
                #pragma unroll
                for (int q = 0; q < 4; q++) acc[i][j][q] = 0.f;
    };

    auto issue_one = [&](const __half* A, const __half* Bw) {   // DMA warp lane 0 only
        mbar_wait(sbase + pslot * 16 + 8, (uint32_t)pph);
        const uint32_t full = sbase + pslot * 16;
        const uint32_t dst  = sbase + SM_TILES + pslot * STAGE_B;
        MBAR_EXPECT_TX(full, (uint32_t)STAGE_B);
        BULK_LD(dst,          A,  (uint32_t)TILE16, full);
        BULK_LD(dst + TILE16, Bw, (uint32_t)TILE16, full);
        if (++pslot == NSLOT) { pslot = 0; pph ^= 1; }
    };

    auto consume_one = [&] {
        mbar_wait(sbase + cslot * 16, (uint32_t)cph);
        const uint32_t ab = sbase + SM_TILES + cslot * STAGE_B;
        const uint32_t bb = ab + TILE16;
        #pragma unroll
        for (int kk = 0; kk < 64; kk += 16) {
            uint32_t a[2][4], b[2][4];
            #pragma unroll
            for (int mf = 0; mf < 2; mf++) {
                const uint32_t off = SWZb((uint32_t)((wm*32 + mf*16 + (lane & 15)) * 128
                                          + kk * 2 + ((lane >> 4) << 4)));
                LDSM4(a[mf][0], a[mf][1], a[mf][2], a[mf][3], ab + off);
            }
            #pragma unroll
            for (int nb = 0; nb < 2; nb++) {
                const uint32_t off = SWZb((uint32_t)((wn*32 + nb*16 + (lane & 15)) * 128
                                          + kk * 2 + ((lane >> 4) << 4)));
                LDSM4(b[nb][0], b[nb][1], b[nb][2], b[nb][3], bb + off);
            }
            #pragma unroll
            for (int mf = 0; mf < 2; mf++)
                #pragma unroll
                for (int nb = 0; nb < 2; nb++) {
                    MMA16816(acc[mf][2*nb],     a[mf], b[nb][0], b[nb][2]);
                    MMA16816(acc[mf][2*nb + 1], a[mf], b[nb][1], b[nb][3]);
                }
        }
        __syncwarp();
        if (lane == 0) MBAR_ARRIVE(sbase + cslot * 16 + 8);
        if (++cslot == NSLOT) { cslot = 0; cph ^= 1; }
    };

    auto epilogue = [&](const float* bias, float* cst, __half* outp, float* h2f) {
        #pragma unroll
        for (int mf = 0; mf < 2; mf++) {
            const int rbase = m0 + wm * 32 + mf * 16 + (lane >> 2) + 8 * (lane & 1);
            #pragma unroll
            for (int nf = 0; nf < 4; nf++) {
                float c0 = acc[mf][nf][0], c1 = acc[mf][nf][1];
                float c2 = acc[mf][nf][2], c3 = acc[mf][nf][3];
                float p0 = __shfl_xor_sync(0xffffffffu, c0, 1);
                float p1 = __shfl_xor_sync(0xffffffffu, c1, 1);
                float p2 = __shfl_xor_sync(0xffffffffu, c2, 1);
                float p3 = __shfl_xor_sync(0xffffffffu, c3, 1);
                float zi, zf, zg, zo;
                if ((lane & 1) == 0) { zi = c0; zf = c1; zg = p0; zo = p1; }
                else                 { zi = p2; zf = p3; zg = c2; zo = c3; }
                const int u = u0 + wn * 8 + nf * 2 + ((lane & 3) >> 1);
                zi += bias[u];
                zf += bias[U_ + u];
                zg += bias[2 * U_ + u];
                zo += bias[3 * U_ + u];
                const size_t gi = (size_t)rbase * U_ + u;
                const float cold = cst[gi];
                const float cn = sigmoidf_(zf) * cold + sigmoidf_(zi) * tanhf_(zg);
                const float hv = sigmoidf_(zo) * tanhf_(cn);
                cst[gi] = cn;
                const uint32_t ho = (uint32_t)(u >> 6) * ACH_E
                                  + (SWZb((uint32_t)rbase * 128 + (uint32_t)(u & 63) * 2) >> 1);
                outp[ho] = __float2half_rn(hv);
                if (h2f) h2f[gi] = hv;
            }
        }
    };

    auto jobA = [&](const JobP& J, int c) -> const __half* {
        return ((c < J.a0n) ? J.a0 + (size_t)c * ACH_E
                            : J.a1 + (size_t)(c - J.a0n) * ACH_E) + (size_t)m0 * 64;
    };

    // run one phase: job0 (+ optional job1). DMA warp streams, consumers compute.
    auto run_phase = [&](const JobP& j0, const float* bias0, float* cst0,
                         __half* out0, float* h2f0,
                         bool two, const JobP& j1, const float* bias1,
                         float* cst1, __half* out1) {
        const int ntot = j0.nch + (two ? j1.nch : 0);
        if (ww == NCW) {
            if (lane == 0) {
                for (int g = 0; g < ntot; g++) {
                    const JobP& J = (g < j0.nch) ? j0 : j1;
                    const int c = (g < j0.nch) ? g : g - j0.nch;
                    issue_one(jobA(J, c), J.Bw + (size_t)c * BCH_E + (size_t)n0 * 64);
                }
            }
        } else {
            zero_acc();
            for (int g = 0; g < ntot; g++) {
                consume_one();
                if (two && g == j0.nch - 1) {
                    epilogue(bias0, cst0, out0, h2f0);
                    zero_acc();
                }
            }
            if (two) epilogue(bias1, cst1, out1, nullptr);
            else     epilogue(bias0, cst0, out0, h2f0);
        }
    };

    unsigned gen = 0;

    // Phase 0: layer1(0) — x(0) + h1_init(buf0, zeros) -> h1(0) in buf1
    {
        JobP j = {NCH1, 1, g_xf, g_h1, g_B1};
        run_phase(j, b1, g_c1, g_h1 + HS, nullptr, false, j, nullptr, nullptr, nullptr);
    }
    grid_sync(++gen);

    // Fused phases: layer2(t) then layer1(t+1)  (both depend only on synced data)
    for (int t = 0; t < T_ - 1; t++) {
        const int rd1 = (t + 1) & 1;   // buffer holding h1(t)
        const int rd2 = t & 1;         // buffer holding h2(t-1)
        JobP jl2 = {NCH2, 8, g_h1 + (size_t)rd1 * HS, g_h2 + (size_t)rd2 * HS, g_B2};
        JobP jl1 = {NCH1, 1, g_xf + (size_t)(t + 1) * ACH_E, g_h1 + (size_t)rd1 * HS, g_B1};
        run_phase(jl2, b2, g_c2, g_h2 + (size_t)(rd2 ^ 1) * HS, g_h2f,
                  true, jl1, b1, g_c1, g_h1 + (size_t)(rd1 ^ 1) * HS);
        grid_sync(++gen);
    }

    // Final phase: layer2(255)
    {
        const int t = T_ - 1;
        const int rd1 = (t + 1) & 1, rd2 = t & 1;
        JobP jl2 = {NCH2, 8, g_h1 + (size_t)rd1 * HS, g_h2 + (size_t)rd2 * HS, g_B2};
        run_phase(jl2, b2, g_c2, g_h2 + (size_t)(rd2 ^ 1) * HS, g_h2f,
                  false, jl2, nullptr, nullptr, nullptr);
    }
    grid_sync(++gen);

    // Dense head: consumer warps only; 128 blocks x 16 warps, first 1024 rows.
    if (ww < NCW) {
        const int w = blockIdx.x * NCW + ww;
        if (w < B_) {
            const float* h = g_h2f + (size_t)w * U_;
            float s = 0.f;
            #pragma unroll
            for (int k = lane; k < U_; k += 32) s += h[k] * Wd[k];
            #pragma unroll
            for (int off = 16; off; off >>= 1) s += __shfl_down_sync(0xffffffffu, s, off);
            if (lane == 0) out[w] = s + bd[0];
        }
    }
}

// ---------------- prep kernels (deterministic, run every replay) ------------
// Weights -> [chunk][n'][64] fp16, SW128-swizzled 128B rows.
__global__ void prep_weights(const float* __restrict__ W1, const float* __restrict__ Uh1,
                             const float* __restrict__ W2, const float* __restrict__ Uh2)
{
    const long total1 = (long)NG * K1;
    const long total  = total1 + (long)NG * K2;
    for (long idx = blockIdx.x * (long)blockDim.x + threadIdx.x; idx < total;
         idx += (long)gridDim.x * blockDim.x) {
        if (idx < total1) {
            const int np = (int)(idx / K1), k = (int)(idx % K1);
            const int n = ((np & 3) << 9) | (np >> 2);
            const float v = (k < D_) ? W1[(size_t)k * NG + n] : Uh1[(size_t)(k - D_) * NG + n];
            const long o = (long)(k >> 6) * BCH_E
                         + (SWZb((uint32_t)np * 128 + (uint32_t)(k & 63) * 2) >> 1);
            g_B1[o] = __float2half_rn(v);
        } else {
            const long i2 = idx - total1;
            const int np = (int)(i2 / K2), k = (int)(i2 % K2);
            const int n = ((np & 3) << 9) | (np >> 2);
            const float v = (k < U_) ? W2[(size_t)k * NG + n] : Uh2[(size_t)(k - U_) * NG + n];
            const long o = (long)(k >> 6) * BCH_E
                         + (SWZb((uint32_t)np * 128 + (uint32_t)(k & 63) * 2) >> 1);
            g_B2[o] = __float2half_rn(v);
        }
    }
}

// x -> [t][m][64] fp16, SW128-swizzled rows
__global__ void prep_x(const float* __restrict__ inputs)
{
    const long total = (long)T_ * B_ * D_;
    for (long idx = blockIdx.x * (long)blockDim.x + threadIdx.x; idx < total;
         idx += (long)gridDim.x * blockDim.x) {
        const int k = (int)(idx & 63);
        const int m = (int)((idx >> 6) & 1023);
        const int t = (int)(idx >> 16);
        const float v = inputs[(size_t)m * (T_ * D_) + (size_t)t * D_ + k];
        const long o = (long)t * ACH_E + (SWZb((uint32_t)m * 128 + (uint32_t)k * 2) >> 1);
        g_xf[o] = __float2half_rn(v);
    }
}

__global__ void init_state()
{
    const int i = blockIdx.x * blockDim.x + threadIdx.x;   // HS threads
    const __half z = __float2half_rn(0.f);
    g_h1[i] = z;                     // buffer 0 (zeros; layout-independent)
    g_h2[i] = z;
    g_c1[i] = 0.f; g_c2[i] = 0.f;
    if (i == 0) { g_count = 0; g_gen = 0; }
}

extern "C" void kernel_launch(void* const* d_in, const int* in_sizes, int n_in,
                              void* d_out, int out_size)
{
    const float* inputs = (const float*)d_in[0];
    const float* W1  = (const float*)d_in[1];
    const float* Uh1 = (const float*)d_in[2];
    const float* b1  = (const float*)d_in[3];
    const float* W2  = (const float*)d_in[4];
    const float* Uh2 = (const float*)d_in[5];
    const float* b2  = (const float*)d_in[6];
    const float* Wd  = (const float*)d_in[7];
    const float* bd  = (const float*)d_in[8];
    float* out = (float*)d_out;

    cudaFuncSetAttribute(lstm_persistent,
                         cudaFuncAttributeMaxDynamicSharedMemorySize, SMEM_DYN);

    prep_weights<<<2048, 256>>>(W1, Uh1, W2, Uh2);
    prep_x<<<4096, 256>>>(inputs);
    init_state<<<HS / 256, 256>>>();
    lstm_persistent<<<NBLK, NT, SMEM_DYN>>>(b1, b2, Wd, bd, out);
}

// round 17
// speedup vs baseline: 1.9481x; 1.9481x over previous
#include <cuda_runtime.h>
#include <cuda_fp16.h>
#include <cstdint>

// Problem dims
#define B_   1024
#define T_   256
#define D_   64
#define U_   512
#define HS   (B_*U_)
#define NG   2048          // 4*U_ gate columns (n' = 4u+g interleaved)
#define K1   (D_ + U_)     // 576
#define K2   (2*U_)        // 1024

#define NT   512
#define NCW  16
#define NBLK 128
#define NCH1 9                        // 1 x-chunk + 8 h1-chunks (64 k each)
#define NCH2 16                       // 8 h1-chunks + 8 h2-chunks
#define NSLOT 3                       // pipeline slots
#define CHSLOT 2                      // chunks per slot
#define TILE16 16384                  // one 128x64 fp16 tile (128B rows, SW128)
#define SLOT_B (CHSLOT*2*TILE16)      // 64KB per slot (A0,B0,A1,B1)
#define SM_TILES 1024                 // mbars in [0, 48): full[i]@16i, empty[i]@16i+8
#define SMEM_DYN (SM_TILES + NSLOT*SLOT_B)   // 197632 B (1 CTA/SM)

// A-chunk (h/x): [chunk][1024 m][64] = 65536 elems, swizzled 128B rows
#define ACH_E 65536
// B-chunk (weights): [chunk][2048 n'][64] = 131072 elems
#define BCH_E 131072

// ---------------- device globals (no allocations allowed) ----------------
__device__ __align__(16) __half g_B1[NG*K1], g_B2[NG*K2];
__device__ __align__(16) __half g_xf[T_*B_*D_];            // [t][m][64] sw
__device__ __align__(16) __half g_h1[2*HS], g_h2[2*HS];    // [buf][8ch][m][64] sw
// c-state in epilogue-permuted coalesced layout: [cta][warp][lane][8]
__device__ __align__(16) float g_c1[HS], g_c2[HS], g_h2f[HS];

// Software grid barrier (monotonic generation; reset each replay)
__device__ unsigned g_count;
__device__ volatile unsigned g_gen;

__device__ __forceinline__ void grid_sync(unsigned gen)
{
    __syncthreads();
    if (threadIdx.x == 0) {
        __threadfence();
        unsigned prev = atomicAdd(&g_count, 1u);
        if (prev == gen * NBLK - 1u) {
            __threadfence();
            g_gen = gen;
        } else {
            while (g_gen < gen) { }
            __threadfence();
        }
    }
    __syncthreads();
}

__device__ __host__ __forceinline__ uint32_t SWZb(uint32_t o) { return o ^ ((o >> 3) & 0x70); }

__device__ __forceinline__ float sigmoidf_(float x) { return 1.0f / (1.0f + __expf(-x)); }
__device__ __forceinline__ float tanhf_(float x) {
    float y; asm("tanh.approx.f32 %0, %1;" : "=f"(y) : "f"(x)); return y;
}
__device__ __forceinline__ uint32_t smem_u32(const void* p) {
    return (uint32_t)__cvta_generic_to_shared(p);
}

#define LDSM4(r0, r1, r2, r3, addr) \
    asm volatile("ldmatrix.sync.aligned.m8n8.x4.shared.b16 {%0,%1,%2,%3}, [%4];" \
        : "=r"(r0), "=r"(r1), "=r"(r2), "=r"(r3) : "r"(addr))

#define MMA16816(c, a, b0_, b1_) \
    asm volatile("mma.sync.aligned.m16n8k16.row.col.f32.f16.f16.f32 " \
        "{%0,%1,%2,%3}, {%4,%5,%6,%7}, {%8,%9}, {%0,%1,%2,%3};" \
        : "+f"((c)[0]), "+f"((c)[1]), "+f"((c)[2]), "+f"((c)[3]) \
        : "r"((a)[0]), "r"((a)[1]), "r"((a)[2]), "r"((a)[3]), "r"(b0_), "r"(b1_))

#define MBAR_INIT(m, cnt) \
    asm volatile("mbarrier.init.shared.b64 [%0], %1;" :: "r"(m), "r"(cnt) : "memory")
#define MBAR_EXPECT_TX(m, bytes) \
    asm volatile("mbarrier.arrive.expect_tx.shared.b64 _, [%0], %1;" :: "r"(m), "r"(bytes) : "memory")
#define MBAR_ARRIVE(m) \
    asm volatile("mbarrier.arrive.shared.b64 _, [%0];" :: "r"(m) : "memory")
#define BULK_LD(dst, src, bytes, m) \
    asm volatile("cp.async.bulk.shared::cta.global.mbarrier::complete_tx::bytes [%0], [%1], %2, [%3];" \
        :: "r"(dst), "l"(src), "r"(bytes), "r"(m) : "memory")

__device__ __forceinline__ void mbar_wait(uint32_t m, uint32_t parity)
{
    asm volatile(
        "{\n\t.reg .pred P;\n\t"
        "WL_%=:\n\t"
        "mbarrier.try_wait.parity.acquire.cta.shared::cta.b64 P, [%0], %1, 0x989680;\n\t"
        "@!P bra WL_%=;\n\t}"
        :: "r"(m), "r"(parity) : "memory");
}

struct JobP { int nch; int a0n; const __half *a0, *a1, *Bw; };

// ---------------- persistent kernel: fused phases + dense head --------------
__global__ __launch_bounds__(NT, 1)
void lstm_persistent(const float* __restrict__ b1, const float* __restrict__ b2,
                     const float* __restrict__ Wd, const float* __restrict__ bd,
                     float* __restrict__ out)
{
    extern __shared__ __align__(1024) char smem[];
    const uint32_t sbase = smem_u32(smem);

    const int tid  = threadIdx.x;
    const int lane = tid & 31;
    const int ww   = tid >> 5;        // 0..15
    const int wm   = ww & 3;          // m group (32 rows)
    const int wn   = ww >> 2;         // n group (32 n' cols)
    const int n0 = (blockIdx.x & 15) * 128;
    const int m0 = (blockIdx.x >> 4) * 128;
    const int u0 = (blockIdx.x & 15) * 32;

    // coalesced per-thread c-state: 8 floats each, [cta][warp][lane][8]
    float* c1p = g_c1 + (size_t)((blockIdx.x * NCW + ww) * 32 + lane) * 8;
    float* c2p = g_c2 + (size_t)((blockIdx.x * NCW + ww) * 32 + lane) * 8;

    // persistent mbarriers: full[i] (tx-arrive), empty[i] (16 warp-arrives)
    if (tid == 0)
        for (int i = 0; i < NSLOT; i++) {
            MBAR_INIT(sbase + i * 16, 1);
            MBAR_INIT(sbase + i * 16 + 8, NCW);
        }
    __syncthreads();

    int pslot = 0, pph = 1;   // producer cursor (empty; fresh barrier passes @parity 1)
    int cslot = 0, cph = 0;   // consumer cursor (full)

    float acc[2][4][4];
    auto zero_acc = [&] {
        #pragma unroll
        for (int i = 0; i < 2; i++)
            #pragma unroll
            for (int j = 0; j < 4; j++)
                #pragma unroll
                for (int q = 0; q < 4; q++) acc[i][j][q] = 0.f;
    };

    auto consume_slot = [&](int len) {
        mbar_wait(sbase + cslot * 16, (uint32_t)cph);
        const uint32_t base = sbase + SM_TILES + cslot * SLOT_B;
        for (int sub = 0; sub < len; sub++) {
            const uint32_t ab = base + sub * (2 * TILE16);
            const uint32_t bb = ab + TILE16;
            #pragma unroll
            for (int kk = 0; kk < 64; kk += 16) {
                uint32_t a[2][4], b[2][4];
                #pragma unroll
                for (int mf = 0; mf < 2; mf++) {
                    const uint32_t off = SWZb((uint32_t)((wm*32 + mf*16 + (lane & 15)) * 128
                                              + kk * 2 + ((lane >> 4) << 4)));
                    LDSM4(a[mf][0], a[mf][1], a[mf][2], a[mf][3], ab + off);
                }
                #pragma unroll
                for (int nb = 0; nb < 2; nb++) {
                    const uint32_t off = SWZb((uint32_t)((wn*32 + nb*16 + (lane & 15)) * 128
                                              + kk * 2 + ((lane >> 4) << 4)));
                    LDSM4(b[nb][0], b[nb][1], b[nb][2], b[nb][3], bb + off);
                }
                #pragma unroll
                for (int mf = 0; mf < 2; mf++)
                    #pragma unroll
                    for (int nb = 0; nb < 2; nb++) {
                        MMA16816(acc[mf][2*nb],     a[mf], b[nb][0], b[nb][2]);
                        MMA16816(acc[mf][2*nb + 1], a[mf], b[nb][1], b[nb][3]);
                    }
            }
        }
        __syncwarp();
        if (lane == 0) MBAR_ARRIVE(sbase + cslot * 16 + 8);
        if (++cslot == NSLOT) { cslot = 0; cph ^= 1; }
    };

    // epilogue: c-state via coalesced per-thread block (2x float4 ld/st)
    auto epilogue = [&](const float* bias, float* cp, __half* outp, float* h2f) {
        float4 cv0 = *reinterpret_cast<const float4*>(cp);
        float4 cv1 = *reinterpret_cast<const float4*>(cp + 4);
        float cold[8] = {cv0.x, cv0.y, cv0.z, cv0.w, cv1.x, cv1.y, cv1.z, cv1.w};
        float cnew[8];
        int idx = 0;
        #pragma unroll
        for (int mf = 0; mf < 2; mf++) {
            const int rbase = m0 + wm * 32 + mf * 16 + (lane >> 2) + 8 * (lane & 1);
            #pragma unroll
            for (int nf = 0; nf < 4; nf++) {
                float c0 = acc[mf][nf][0], c1 = acc[mf][nf][1];
                float c2 = acc[mf][nf][2], c3 = acc[mf][nf][3];
                float p0 = __shfl_xor_sync(0xffffffffu, c0, 1);
                float p1 = __shfl_xor_sync(0xffffffffu, c1, 1);
                float p2 = __shfl_xor_sync(0xffffffffu, c2, 1);
                float p3 = __shfl_xor_sync(0xffffffffu, c3, 1);
                float zi, zf, zg, zo;
                if ((lane & 1) == 0) { zi = c0; zf = c1; zg = p0; zo = p1; }
                else                 { zi = p2; zf = p3; zg = c2; zo = c3; }
                const int u = u0 + wn * 8 + nf * 2 + ((lane & 3) >> 1);
                zi += bias[u];
                zf += bias[U_ + u];
                zg += bias[2 * U_ + u];
                zo += bias[3 * U_ + u];
                const float cn = sigmoidf_(zf) * cold[idx] + sigmoidf_(zi) * tanhf_(zg);
                const float hv = sigmoidf_(zo) * tanhf_(cn);
                cnew[idx] = cn;
                const uint32_t ho = (uint32_t)(u >> 6) * ACH_E
                                  + (SWZb((uint32_t)rbase * 128 + (uint32_t)(u & 63) * 2) >> 1);
                outp[ho] = __float2half_rn(hv);
                if (h2f) h2f[(size_t)rbase * U_ + u] = hv;
                idx++;
            }
        }
        *reinterpret_cast<float4*>(cp)     = make_float4(cnew[0], cnew[1], cnew[2], cnew[3]);
        *reinterpret_cast<float4*>(cp + 4) = make_float4(cnew[4], cnew[5], cnew[6], cnew[7]);
    };

    auto jobA = [&](const JobP& J, int c) -> const __half* {
        return ((c < J.a0n) ? J.a0 + (size_t)c * ACH_E
                            : J.a1 + (size_t)(c - J.a0n) * ACH_E) + (size_t)m0 * 64;
    };

    // run one phase: job0 (+ optional job1), 2-chunk slots, decoupled ring
    auto run_phase = [&](const JobP& j0, const float* bias0, float* cp0,
                         __half* out0,
                         bool two, const JobP& j1, const float* bias1,
                         float* cp1, __half* out1, float* h2f_final) {
        // slot table (slots never span the job boundary; j0.nch=16 -> exact)
        int spos[16], slen[16], nst = 0;
        for (int pos = 0; pos < j0.nch; ) {
            int l = (j0.nch - pos < CHSLOT) ? (j0.nch - pos) : CHSLOT;
            spos[nst] = pos; slen[nst] = l; nst++; pos += l;
        }
        const int j0slots = nst;
        if (two)
            for (int pos = 0; pos < j1.nch; ) {
                int l = (j1.nch - pos < CHSLOT) ? (j1.nch - pos) : CHSLOT;
                spos[nst] = j0.nch + pos; slen[nst] = l; nst++; pos += l;
            }

        auto issue_slot = [&](int s) {    // tid 0 only
            mbar_wait(sbase + pslot * 16 + 8, (uint32_t)pph);
            const uint32_t full = sbase + pslot * 16;
            const uint32_t dst  = sbase + SM_TILES + pslot * SLOT_B;
            MBAR_EXPECT_TX(full, (uint32_t)(slen[s] * 2 * TILE16));
            for (int sub = 0; sub < slen[s]; sub++) {
                const int g = spos[s] + sub;
                const JobP& J = (g < j0.nch) ? j0 : j1;
                const int c = (g < j0.nch) ? g : g - j0.nch;
                BULK_LD(dst + sub * (2 * TILE16),          jobA(J, c), (uint32_t)TILE16, full);
                BULK_LD(dst + sub * (2 * TILE16) + TILE16,
                        J.Bw + (size_t)c * BCH_E + (size_t)n0 * 64, (uint32_t)TILE16, full);
            }
            if (++pslot == NSLOT) { pslot = 0; pph ^= 1; }
        };

        if (tid == 0) { issue_slot(0); if (nst > 1) issue_slot(1); }
        zero_acc();
        for (int s = 0; s < nst; s++) {
            if (tid == 0 && s + 2 < nst) issue_slot(s + 2);
            consume_slot(slen[s]);
            if (two && s == j0slots - 1) {
                epilogue(bias0, cp0, out0, nullptr);
                zero_acc();
            }
        }
        if (two) epilogue(bias1, cp1, out1, nullptr);
        else     epilogue(bias0, cp0, out0, h2f_final);
    };

    unsigned gen = 0;

    // Phase 0: layer1(0) — x(0) + h1_init(buf0, zeros) -> h1(0) in buf1
    {
        JobP j = {NCH1, 1, g_xf, g_h1, g_B1};
        run_phase(j, b1, c1p, g_h1 + HS, false, j, nullptr, nullptr, nullptr, nullptr);
    }
    grid_sync(++gen);

    // Fused phases: layer2(t) then layer1(t+1)
    for (int t = 0; t < T_ - 1; t++) {
        const int rd1 = (t + 1) & 1;   // buffer holding h1(t)
        const int rd2 = t & 1;         // buffer holding h2(t-1)
        JobP jl2 = {NCH2, 8, g_h1 + (size_t)rd1 * HS, g_h2 + (size_t)rd2 * HS, g_B2};
        JobP jl1 = {NCH1, 1, g_xf + (size_t)(t + 1) * ACH_E, g_h1 + (size_t)rd1 * HS, g_B1};
        run_phase(jl2, b2, c2p, g_h2 + (size_t)(rd2 ^ 1) * HS,
                  true, jl1, b1, c1p, g_h1 + (size_t)(rd1 ^ 1) * HS, nullptr);
        grid_sync(++gen);
    }

    // Final phase: layer2(255) — only here is h2f written (dense head input)
    {
        const int t = T_ - 1;
        const int rd1 = (t + 1) & 1, rd2 = t & 1;
        JobP jl2 = {NCH2, 8, g_h1 + (size_t)rd1 * HS, g_h2 + (size_t)rd2 * HS, g_B2};
        run_phase(jl2, b2, c2p, g_h2 + (size_t)(rd2 ^ 1) * HS,
                  false, jl2, nullptr, nullptr, nullptr, g_h2f);
    }
    grid_sync(++gen);

    // Dense head: 128 blocks x 16 warps = 2048 warps; first 1024 take one row.
    const int w = blockIdx.x * NCW + ww;
    if (w < B_) {
        const float* h = g_h2f + (size_t)w * U_;
        float s = 0.f;
        #pragma unroll
        for (int k = lane; k < U_; k += 32) s += h[k] * Wd[k];
        #pragma unroll
        for (int off = 16; off; off >>= 1) s += __shfl_down_sync(0xffffffffu, s, off);
        if (lane == 0) out[w] = s + bd[0];
    }
}

// ---------------- prep kernels (deterministic, run every replay) ------------
// Weights -> [chunk][n'][64] fp16, SW128-swizzled 128B rows.
__global__ void prep_weights(const float* __restrict__ W1, const float* __restrict__ Uh1,
                             const float* __restrict__ W2, const float* __restrict__ Uh2)
{
    const long total1 = (long)NG * K1;
    const long total  = total1 + (long)NG * K2;
    for (long idx = blockIdx.x * (long)blockDim.x + threadIdx.x; idx < total;
         idx += (long)gridDim.x * blockDim.x) {
        if (idx < total1) {
            const int np = (int)(idx / K1), k = (int)(idx % K1);
            const int n = ((np & 3) << 9) | (np >> 2);
            const float v = (k < D_) ? W1[(size_t)k * NG + n] : Uh1[(size_t)(k - D_) * NG + n];
            const long o = (long)(k >> 6) * BCH_E
                         + (SWZb((uint32_t)np * 128 + (uint32_t)(k & 63) * 2) >> 1);
            g_B1[o] = __float2half_rn(v);
        } else {
            const long i2 = idx - total1;
            const int np = (int)(i2 / K2), k = (int)(i2 % K2);
            const int n = ((np & 3) << 9) | (np >> 2);
            const float v = (k < U_) ? W2[(size_t)k * NG + n] : Uh2[(size_t)(k - U_) * NG + n];
            const long o = (long)(k >> 6) * BCH_E
                         + (SWZb((uint32_t)np * 128 + (uint32_t)(k & 63) * 2) >> 1);
            g_B2[o] = __float2half_rn(v);
        }
    }
}

// x -> [t][m][64] fp16, SW128-swizzled rows
__global__ void prep_x(const float* __restrict__ inputs)
{
    const long total = (long)T_ * B_ * D_;
    for (long idx = blockIdx.x * (long)blockDim.x + threadIdx.x; idx < total;
         idx += (long)gridDim.x * blockDim.x) {
        const int k = (int)(idx & 63);
        const int m = (int)((idx >> 6) & 1023);
        const int t = (int)(idx >> 16);
        const float v = inputs[(size_t)m * (T_ * D_) + (size_t)t * D_ + k];
        const long o = (long)t * ACH_E + (SWZb((uint32_t)m * 128 + (uint32_t)k * 2) >> 1);
        g_xf[o] = __float2half_rn(v);
    }
}

__global__ void init_state()
{
    const int i = blockIdx.x * blockDim.x + threadIdx.x;   // HS threads
    const __half z = __float2half_rn(0.f);
    g_h1[i] = z;                     // buffer 0 (zeros; layout-independent)
    g_h2[i] = z;
    g_c1[i] = 0.f; g_c2[i] = 0.f;    // permuted layout; zeros everywhere
    if (i == 0) { g_count = 0; g_gen = 0; }
}

extern "C" void kernel_launch(void* const* d_in, const int* in_sizes, int n_in,
                              void* d_out, int out_size)
{
    const float* inputs = (const float*)d_in[0];
    const float* W1  = (const float*)d_in[1];
    const float* Uh1 = (const float*)d_in[2];
    const float* b1  = (const float*)d_in[3];
    const float* W2  = (const float*)d_in[4];
    const float* Uh2 = (const float*)d_in[5];
    const float* b2  = (const float*)d_in[6];
    const float* Wd  = (const float*)d_in[7];
    const float* bd  = (const float*)d_in[8];
    float* out = (float*)d_out;

    cudaFuncSetAttribute(lstm_persistent,
                         cudaFuncAttributeMaxDynamicSharedMemorySize, SMEM_DYN);

    prep_weights<<<2048, 256>>>(W1, Uh1, W2, Uh2);
    prep_x<<<4096, 256>>>(inputs);
    init_state<<<HS / 256, 256>>>();
    lstm_persistent<<<NBLK, NT, SMEM_DYN>>>(b1, b2, Wd, bd, out);
}